// round 1
// baseline (speedup 1.0000x reference)
#include <cuda_runtime.h>
#include <math.h>

// Problem constants
#define B_SZ 4
#define T_SZ 4096
#define DM   1024            // d_model
#define HS   1024            // n_heads * d_state
#define GN   3072            // fused N: forget(1024) | input(1024) | value(1024)
#define M_SZ (B_SZ * T_SZ)   // 16384 rows
#define NCHUNK 64
#define LCHUNK (T_SZ / NCHUNK)

// Scratch (device globals: allocation-free per harness rules)
__device__ __align__(128) float g_G[(size_t)M_SZ * GN];   // [M, 3072]: A-pre | IG-pre | V (post-activation stored)
__device__ __align__(128) float g_h[(size_t)M_SZ * HS];   // h_flat [M, 1024]
__device__ __align__(128) float g_P [B_SZ * HS * NCHUNK]; // per-chunk prod(a)
__device__ __align__(128) float g_Hl[B_SZ * HS * NCHUNK]; // per-chunk local h
__device__ __align__(128) float g_C [B_SZ * HS * NCHUNK]; // per-chunk carry-in

// ---------------------------------------------------------------------------
// Tiled fp32 SGEMM: C[M,N] = A[M,K] * W[N,K]^T  (both operands K-contiguous)
// BM=BN=128, BK=16, 256 threads, 8x8 register tile per thread.
// W tile pointer selected per N-block: cols < split -> W0, else W1.
// Epilogue: cols < split get +bias then sigmoid.
// toG: write into g_G (device symbol) instead of Cext.
// aFromH: read A from g_h (device symbol) instead of A param.
// ---------------------------------------------------------------------------
__global__ __launch_bounds__(256, 2) void sgemm_k(
    const float* __restrict__ A,
    const float* __restrict__ W0,
    const float* __restrict__ W1,
    const float* __restrict__ bias,
    float* __restrict__ Cext,
    int N, int K, int split, int toG, int aFromH)
{
    const int m0 = blockIdx.y * 128;
    const int n0 = blockIdx.x * 128;

    const float* Abase = aFromH ? (const float*)g_h : A;
    const float* Ap = Abase + (size_t)m0 * K;
    const float* Bp = (n0 < split) ? (W0 + (size_t)n0 * K)
                                   : (W1 + (size_t)(n0 - split) * K);
    float* C = toG ? (float*)g_G : Cext;

    __shared__ float As[16][132];
    __shared__ float Bs[16][132];

    const int tid  = threadIdx.x;
    const int tx   = tid & 15;        // 0..15 -> N sub-tile
    const int ty   = tid >> 4;        // 0..15 -> M sub-tile
    const int lrow = tid >> 2;        // 0..63 load row
    const int lcol = (tid & 3) << 2;  // k offset 0,4,8,12

    float acc[8][8] = {};

    for (int k0 = 0; k0 < K; k0 += 16) {
        #pragma unroll
        for (int r = 0; r < 2; r++) {
            int m = lrow + r * 64;
            float4 va = *(const float4*)(Ap + (size_t)m * K + k0 + lcol);
            As[lcol + 0][m] = va.x; As[lcol + 1][m] = va.y;
            As[lcol + 2][m] = va.z; As[lcol + 3][m] = va.w;
            float4 vb = *(const float4*)(Bp + (size_t)m * K + k0 + lcol);
            Bs[lcol + 0][m] = vb.x; Bs[lcol + 1][m] = vb.y;
            Bs[lcol + 2][m] = vb.z; Bs[lcol + 3][m] = vb.w;
        }
        __syncthreads();

        #pragma unroll
        for (int k = 0; k < 16; k++) {
            float4 a0 = *(const float4*)&As[k][ty * 8];
            float4 a1 = *(const float4*)&As[k][ty * 8 + 4];
            float4 b0 = *(const float4*)&Bs[k][tx * 8];
            float4 b1 = *(const float4*)&Bs[k][tx * 8 + 4];
            float ar[8] = {a0.x, a0.y, a0.z, a0.w, a1.x, a1.y, a1.z, a1.w};
            float br[8] = {b0.x, b0.y, b0.z, b0.w, b1.x, b1.y, b1.z, b1.w};
            #pragma unroll
            for (int i = 0; i < 8; i++)
                #pragma unroll
                for (int j = 0; j < 8; j++)
                    acc[i][j] = fmaf(ar[i], br[j], acc[i][j]);
        }
        __syncthreads();
    }

    const bool sig = (n0 < split);
    #pragma unroll
    for (int i = 0; i < 8; i++) {
        int gm = m0 + ty * 8 + i;
        float* crow = C + (size_t)gm * N + n0 + tx * 8;
        #pragma unroll
        for (int j = 0; j < 8; j++) {
            float v = acc[i][j];
            if (sig) {
                v += bias[n0 + tx * 8 + j];
                v = 1.f / (1.f + __expf(-v));
            }
            crow[j] = v;
        }
    }
}

// ---------------------------------------------------------------------------
// Chunked scan. Channel c = b*1024 + i. Per t row of g_G:
//   a = sigmoid(forget) at col i, ig = sigmoid(input) at col 1024+i, v at 2048+i
//   h = a*h + ig*v
// Phase 1: per (b, chunk): prod(a) and local h (carry-free).
// ---------------------------------------------------------------------------
__global__ __launch_bounds__(HS) void scan_phase1()
{
    const int b = blockIdx.y, chunk = blockIdx.x, i = threadIdx.x;
    const int t0 = chunk * LCHUNK;
    const float* base = g_G + (size_t)(b * T_SZ + t0) * GN;

    float p = 1.f, hl = 0.f;
    for (int t = 0; t < LCHUNK; t++) {
        const float* row = base + (size_t)t * GN;
        float a = row[i], ig = row[HS + i], v = row[2 * HS + i];
        p *= a;
        hl = fmaf(a, hl, ig * v);
    }
    const int c = b * HS + i;
    g_P [c * NCHUNK + chunk] = p;
    g_Hl[c * NCHUNK + chunk] = hl;
}

// Phase 2: sequential combine of 64 chunk summaries per channel (4096 threads).
__global__ void scan_phase2(const float* __restrict__ h_prev,
                            float* __restrict__ h_last_out)
{
    const int c = blockIdx.x * blockDim.x + threadIdx.x;  // 0..4095
    float carry = h_prev[c];
    #pragma unroll
    for (int j = 0; j < NCHUNK; j++) {
        g_C[c * NCHUNK + j] = carry;
        carry = fmaf(g_P[c * NCHUNK + j], carry, g_Hl[c * NCHUNK + j]);
    }
    h_last_out[c] = carry;
}

// Phase 3: rescan each chunk with its carry-in, emit h_flat.
__global__ __launch_bounds__(HS) void scan_phase3()
{
    const int b = blockIdx.y, chunk = blockIdx.x, i = threadIdx.x;
    const int c = b * HS + i;
    const int t0 = chunk * LCHUNK;
    const float* base  = g_G + (size_t)(b * T_SZ + t0) * GN;
    float*       hbase = g_h + (size_t)(b * T_SZ + t0) * HS;

    float h = g_C[c * NCHUNK + chunk];
    for (int t = 0; t < LCHUNK; t++) {
        const float* row = base + (size_t)t * GN;
        float a = row[i], ig = row[HS + i], v = row[2 * HS + i];
        h = fmaf(a, h, ig * v);
        hbase[(size_t)t * HS + i] = h;
    }
}

// ---------------------------------------------------------------------------
// Inputs (metadata order): x, h_prev, gate_w, gate_b, value_w, out_w
// Output: y [B,T,DM] flattened, then h_last [B,H,S] (4096 floats)
// ---------------------------------------------------------------------------
extern "C" void kernel_launch(void* const* d_in, const int* in_sizes, int n_in,
                              void* d_out, int out_size)
{
    const float* x       = (const float*)d_in[0];
    const float* h_prev  = (const float*)d_in[1];
    const float* gate_w  = (const float*)d_in[2];
    const float* gate_b  = (const float*)d_in[3];
    const float* value_w = (const float*)d_in[4];
    const float* out_w   = (const float*)d_in[5];

    float* y      = (float*)d_out;
    float* h_last = y + (size_t)M_SZ * DM;

    // GEMM1: gates (sigmoid+bias) and V into g_G
    dim3 g1(GN / 128, M_SZ / 128);
    sgemm_k<<<g1, 256>>>(x, gate_w, value_w, gate_b, nullptr,
                         GN, DM, /*split=*/2048, /*toG=*/1, /*aFromH=*/0);

    // Scan
    scan_phase1<<<dim3(NCHUNK, B_SZ), HS>>>();
    scan_phase2<<<B_SZ, HS>>>(h_prev, h_last);
    scan_phase3<<<dim3(NCHUNK, B_SZ), HS>>>();

    // GEMM2: y = h_flat @ out_w^T
    dim3 g2(DM / 128, M_SZ / 128);
    sgemm_k<<<g2, 256>>>(nullptr, nullptr, out_w, nullptr, y,
                         DM, HS, /*split=*/0, /*toG=*/0, /*aFromH=*/1);
}

// round 7
// speedup vs baseline: 1.7698x; 1.7698x over previous
#include <cuda_runtime.h>
#include <cuda_bf16.h>
#include <stdint.h>
#include <math.h>

#define B_SZ 4
#define T_SZ 4096
#define DM   1024
#define HS   1024
#define GN   3072
#define M_SZ (B_SZ * T_SZ)
#define NCHUNK 64
#define LCHUNK (T_SZ / NCHUNK)
#define BK 16                    // K per SMEM stage (one m16n8k16 k-step)

// ---------------- scratch (device globals; allocation-free) ----------------
__device__ __align__(128) float g_G[(size_t)M_SZ * GN];     // sigmoid(gates) | V
__device__ __align__(128) float g_P [B_SZ * HS * NCHUNK];
__device__ __align__(128) float g_Hl[B_SZ * HS * NCHUNK];
__device__ __align__(128) float g_C [B_SZ * HS * NCHUNK];
__device__ __align__(128) __nv_bfloat16 g_xh[(size_t)M_SZ * DM], g_xl[(size_t)M_SZ * DM];
__device__ __align__(128) __nv_bfloat16 g_w1h[(size_t)GN * DM],  g_w1l[(size_t)GN * DM];
__device__ __align__(128) __nv_bfloat16 g_w2h[(size_t)DM * HS],  g_w2l[(size_t)DM * HS];
__device__ __align__(128) __nv_bfloat16 g_hh[(size_t)M_SZ * HS], g_hl[(size_t)M_SZ * HS];

// ---------------- PTX helpers (sm_80-era: compile on plain compute_103) ----
__device__ __forceinline__ uint32_t smem_u32(const void* p) {
    uint32_t a;
    asm("{ .reg .u64 t; cvta.to.shared.u64 t, %1; cvt.u32.u64 %0, t; }" : "=r"(a) : "l"(p));
    return a;
}
__device__ __forceinline__ void cp16(uint32_t s, const void* g) {
    asm volatile("cp.async.cg.shared.global [%0], [%1], 16;" :: "r"(s), "l"(g));
}
__device__ __forceinline__ void cp_commit() {
    asm volatile("cp.async.commit_group;");
}
__device__ __forceinline__ void ldsm4(uint32_t* r, uint32_t addr) {
    asm volatile("ldmatrix.sync.aligned.m8n8.x4.shared.b16 {%0,%1,%2,%3}, [%4];"
                 : "=r"(r[0]), "=r"(r[1]), "=r"(r[2]), "=r"(r[3]) : "r"(addr));
}
__device__ __forceinline__ void mma16816(float* d, const uint32_t* a,
                                         uint32_t b0, uint32_t b1) {
    asm volatile("mma.sync.aligned.m16n8k16.row.col.f32.bf16.bf16.f32 "
                 "{%0,%1,%2,%3}, {%4,%5,%6,%7}, {%8,%9}, {%0,%1,%2,%3};"
                 : "+f"(d[0]), "+f"(d[1]), "+f"(d[2]), "+f"(d[3])
                 : "r"(a[0]), "r"(a[1]), "r"(a[2]), "r"(a[3]), "r"(b0), "r"(b1));
}

// swizzled smem byte offset for a [row][16B-chunk] of a 128x16 bf16 tile (32B rows)
__device__ __forceinline__ uint32_t swz(int row, int chunk) {
    return (uint32_t)(row * 32 + ((chunk ^ ((row >> 2) & 1)) << 4));
}

// ---------------- hi/lo bf16 split of fp32 inputs ----------------
__global__ void split_k(const float* __restrict__ src, int mode, int n4)
{
    int i = blockIdx.x * blockDim.x + threadIdx.x;
    if (i >= n4) return;
    __nv_bfloat16 *hi, *lo;
    size_t off = 0;
    if (mode == 0)      { hi = g_xh;  lo = g_xl; }
    else if (mode == 1) { hi = g_w1h; lo = g_w1l; }
    else if (mode == 2) { hi = g_w1h; lo = g_w1l; off = (size_t)2048 * 1024; }
    else                { hi = g_w2h; lo = g_w2l; }
    float4 v = ((const float4*)src)[i];
    float x[4] = {v.x, v.y, v.z, v.w};
    __align__(8) __nv_bfloat16 h[4];
    __align__(8) __nv_bfloat16 l[4];
    #pragma unroll
    for (int j = 0; j < 4; j++) {
        h[j] = __float2bfloat16(x[j]);
        l[j] = __float2bfloat16(x[j] - __bfloat162float(h[j]));
    }
    *(uint2*)(hi + off + (size_t)i * 4) = *(uint2*)h;
    *(uint2*)(lo + off + (size_t)i * 4) = *(uint2*)l;
}

// ---------------- HMMA bf16x3 GEMM: C[M,N] = A[M,K] * W[N,K]^T ------------
// mode 0: A = x(hi/lo), B = [gate_w|value_w](hi/lo), C = g_G, sigmoid+bias on cols<nsplit
// mode 1: A = h(hi/lo), B = out_w(hi/lo),            C = Cext (y)
__global__ __launch_bounds__(256, 1)
void tc_gemm(int mode, const float* __restrict__ bias, float* __restrict__ Cext,
             int N, int nsplit)
{
    // [stage][array: Ah,Al,Bh,Bl][128*16 bf16]
    __shared__ __align__(1024) __nv_bfloat16 sm[2][4][128 * BK];

    const int tid = threadIdx.x;
    const int lane = tid & 31, warp = tid >> 5;
    const int wm = warp & 3, wn = warp >> 2;       // warp grid 4 (m) x 2 (n)
    const int m0 = blockIdx.y * 128, n0 = blockIdx.x * 128;
    const int K = DM;                              // both GEMMs have K=1024

    const __nv_bfloat16 *Ah, *Al, *Bh, *Bl;
    float* C;
    if (mode == 0) { Ah = g_xh; Al = g_xl; Bh = g_w1h; Bl = g_w1l; C = g_G; }
    else           { Ah = g_hh; Al = g_hl; Bh = g_w2h; Bl = g_w2l; C = Cext; }

    // global load coords: 256 threads x 16B covers one 128x16 bf16 array
    const int lrow = tid >> 1;            // 0..127
    const int lu   = tid & 1;             // 16B chunk within 32B row
    const uint32_t so = swz(lrow, lu);
    const size_t gA = (size_t)(m0 + lrow) * K + lu * 8;
    const size_t gB = (size_t)(n0 + lrow) * K + lu * 8;

    uint32_t sbase[2][4];
    #pragma unroll
    for (int s = 0; s < 2; s++)
        #pragma unroll
        for (int a = 0; a < 4; a++)
            sbase[s][a] = smem_u32(&sm[s][a][0]);

    float acc[2][8][4] = {};

    // ldmatrix addresses (row/chunk within tile) — fixed per thread
    const int fr = lane & 15;             // row within 16-row tile
    const int fh = lane >> 4;             // k half (16B chunk 0/1)

    // prologue: stage 0 = chunk 0
    cp16(sbase[0][0] + so, Ah + gA);
    cp16(sbase[0][1] + so, Al + gA);
    cp16(sbase[0][2] + so, Bh + gB);
    cp16(sbase[0][3] + so, Bl + gB);
    cp_commit();

    const int NCH = K / BK;               // 64
    for (int ch = 0; ch < NCH; ch++) {
        const int st = ch & 1;
        if (ch + 1 < NCH) {
            const size_t ko = (size_t)(ch + 1) * BK;
            const int ns = st ^ 1;
            cp16(sbase[ns][0] + so, Ah + gA + ko);
            cp16(sbase[ns][1] + so, Al + gA + ko);
            cp16(sbase[ns][2] + so, Bh + gB + ko);
            cp16(sbase[ns][3] + so, Bl + gB + ko);
            cp_commit();
            asm volatile("cp.async.wait_group 1;");
        } else {
            asm volatile("cp.async.wait_group 0;");
        }
        __syncthreads();

        // fragments
        uint32_t ah[2][4], al[2][4], bh[4][4], bl[4][4];
        #pragma unroll
        for (int am = 0; am < 2; am++) {
            int row = wm * 32 + am * 16 + fr;
            uint32_t off = swz(row, fh);
            ldsm4(ah[am], sbase[st][0] + off);
            ldsm4(al[am], sbase[st][1] + off);
        }
        #pragma unroll
        for (int nt = 0; nt < 4; nt++) {
            int row = wn * 64 + nt * 16 + fr;
            uint32_t off = swz(row, fh);
            ldsm4(bh[nt], sbase[st][2] + off);
            ldsm4(bl[nt], sbase[st][3] + off);
        }

        // 3-pass precision-split MMA: Ah*Bh + Ah*Bl + Al*Bh
        #pragma unroll
        for (int am = 0; am < 2; am++)
            #pragma unroll
            for (int nt = 0; nt < 4; nt++) {
                mma16816(acc[am][nt * 2 + 0], ah[am], bh[nt][0], bh[nt][2]);
                mma16816(acc[am][nt * 2 + 1], ah[am], bh[nt][1], bh[nt][3]);
                mma16816(acc[am][nt * 2 + 0], ah[am], bl[nt][0], bl[nt][2]);
                mma16816(acc[am][nt * 2 + 1], ah[am], bl[nt][1], bl[nt][3]);
                mma16816(acc[am][nt * 2 + 0], al[am], bh[nt][0], bh[nt][2]);
                mma16816(acc[am][nt * 2 + 1], al[am], bh[nt][1], bh[nt][3]);
            }
        __syncthreads();
    }

    // epilogue: d0,d1 -> (row, col..col+1); d2,d3 -> (row+8, same cols)
    #pragma unroll
    for (int am = 0; am < 2; am++) {
        int row = m0 + wm * 32 + am * 16 + (lane >> 2);
        #pragma unroll
        for (int bn = 0; bn < 8; bn++) {
            int col = n0 + wn * 64 + bn * 8 + (lane & 3) * 2;
            float* d = acc[am][bn];
            float v0 = d[0], v1 = d[1], v2 = d[2], v3 = d[3];
            if (col < nsplit) {
                float b0 = bias[col], b1 = bias[col + 1];
                v0 = 1.f / (1.f + __expf(-(v0 + b0)));
                v1 = 1.f / (1.f + __expf(-(v1 + b1)));
                v2 = 1.f / (1.f + __expf(-(v2 + b0)));
                v3 = 1.f / (1.f + __expf(-(v3 + b1)));
            }
            *(float2*)(C + (size_t)row * N + col)       = make_float2(v0, v1);
            *(float2*)(C + (size_t)(row + 8) * N + col) = make_float2(v2, v3);
        }
    }
}

// ---------------- chunked scan ----------------
__global__ __launch_bounds__(HS) void scan_phase1()
{
    const int b = blockIdx.y, chunk = blockIdx.x, i = threadIdx.x;
    const int t0 = chunk * LCHUNK;
    const float* base = g_G + (size_t)(b * T_SZ + t0) * GN;
    float p = 1.f, hl = 0.f;
    for (int t = 0; t < LCHUNK; t++) {
        const float* row = base + (size_t)t * GN;
        float a = row[i], ig = row[HS + i], v = row[2 * HS + i];
        p *= a;
        hl = fmaf(a, hl, ig * v);
    }
    const int c = b * HS + i;
    g_P [c * NCHUNK + chunk] = p;
    g_Hl[c * NCHUNK + chunk] = hl;
}

__global__ void scan_phase2(const float* __restrict__ h_prev,
                            float* __restrict__ h_last_out)
{
    const int c = blockIdx.x * blockDim.x + threadIdx.x;
    float carry = h_prev[c];
    #pragma unroll
    for (int j = 0; j < NCHUNK; j++) {
        g_C[c * NCHUNK + j] = carry;
        carry = fmaf(g_P[c * NCHUNK + j], carry, g_Hl[c * NCHUNK + j]);
    }
    h_last_out[c] = carry;
}

// phase3 emits h directly as bf16 hi/lo for GEMM2
__global__ __launch_bounds__(HS) void scan_phase3()
{
    const int b = blockIdx.y, chunk = blockIdx.x, i = threadIdx.x;
    const int c = b * HS + i;
    const int t0 = chunk * LCHUNK;
    const float* base = g_G + (size_t)(b * T_SZ + t0) * GN;
    const size_t hb = (size_t)(b * T_SZ + t0) * HS;

    float h = g_C[c * NCHUNK + chunk];
    for (int t = 0; t < LCHUNK; t++) {
        const float* row = base + (size_t)t * GN;
        float a = row[i], ig = row[HS + i], v = row[2 * HS + i];
        h = fmaf(a, h, ig * v);
        __nv_bfloat16 hh = __float2bfloat16(h);
        g_hh[hb + (size_t)t * HS + i] = hh;
        g_hl[hb + (size_t)t * HS + i] = __float2bfloat16(h - __bfloat162float(hh));
    }
}

// ---------------- launch ----------------
extern "C" void kernel_launch(void* const* d_in, const int* in_sizes, int n_in,
                              void* d_out, int out_size)
{
    const float* x       = (const float*)d_in[0];
    const float* h_prev  = (const float*)d_in[1];
    const float* gate_w  = (const float*)d_in[2];
    const float* gate_b  = (const float*)d_in[3];
    const float* value_w = (const float*)d_in[4];
    const float* out_w   = (const float*)d_in[5];

    float* y      = (float*)d_out;
    float* h_last = y + (size_t)M_SZ * DM;

    // hi/lo splits
    split_k<<<(M_SZ * DM / 4 + 255) / 256, 256>>>(x,       0, M_SZ * DM / 4);
    split_k<<<(2048 * 1024 / 4 + 255) / 256, 256>>>(gate_w, 1, 2048 * 1024 / 4);
    split_k<<<(1024 * 1024 / 4 + 255) / 256, 256>>>(value_w,2, 1024 * 1024 / 4);
    split_k<<<(1024 * 1024 / 4 + 255) / 256, 256>>>(out_w,  3, 1024 * 1024 / 4);

    // GEMM1: sigmoid(gates)+bias (cols<2048) and V -> g_G
    tc_gemm<<<dim3(GN / 128, M_SZ / 128), 256>>>(0, gate_b, nullptr, GN, 2048);

    // scan
    scan_phase1<<<dim3(NCHUNK, B_SZ), HS>>>();
    scan_phase2<<<B_SZ, HS>>>(h_prev, h_last);
    scan_phase3<<<dim3(NCHUNK, B_SZ), HS>>>();

    // GEMM2: y = h @ out_w^T
    tc_gemm<<<dim3(DM / 128, M_SZ / 128), 256>>>(1, nullptr, y, DM, 0);
}

// round 9
// speedup vs baseline: 2.0917x; 1.1819x over previous
#include <cuda_runtime.h>
#include <cuda_bf16.h>
#include <stdint.h>
#include <math.h>

#define B_SZ 4
#define T_SZ 4096
#define DM   1024
#define HS   1024
#define GN   3072
#define M_SZ (B_SZ * T_SZ)
#define NCHUNK 64
#define LCHUNK (T_SZ / NCHUNK)
#define BK 16                    // K per SMEM stage (one m16n8k16 k-step)
#define NSTAGE 3

// ---------------- scratch (device globals; allocation-free) ----------------
__device__ __align__(128) float g_G[(size_t)M_SZ * GN];     // sigmoid(gates) | V
__device__ __align__(128) float g_P [B_SZ * HS * NCHUNK];
__device__ __align__(128) float g_Hl[B_SZ * HS * NCHUNK];
__device__ __align__(128) float g_C [B_SZ * HS * NCHUNK];
__device__ __align__(128) __nv_bfloat16 g_xh[(size_t)M_SZ * DM], g_xl[(size_t)M_SZ * DM];
__device__ __align__(128) __nv_bfloat16 g_w1h[(size_t)GN * DM],  g_w1l[(size_t)GN * DM];
__device__ __align__(128) __nv_bfloat16 g_w2h[(size_t)DM * HS],  g_w2l[(size_t)DM * HS];
__device__ __align__(128) __nv_bfloat16 g_hh[(size_t)M_SZ * HS], g_hl[(size_t)M_SZ * HS];

// ---------------- PTX helpers (sm_80-era; compile on plain compute_103) ----
__device__ __forceinline__ uint32_t smem_u32(const void* p) {
    uint32_t a;
    asm("{ .reg .u64 t; cvta.to.shared.u64 t, %1; cvt.u32.u64 %0, t; }" : "=r"(a) : "l"(p));
    return a;
}
__device__ __forceinline__ void cp16(uint32_t s, const void* g) {
    asm volatile("cp.async.cg.shared.global [%0], [%1], 16;" :: "r"(s), "l"(g));
}
__device__ __forceinline__ void cp_commit() {
    asm volatile("cp.async.commit_group;");
}
__device__ __forceinline__ void ldsm4(uint32_t* r, uint32_t addr) {
    asm volatile("ldmatrix.sync.aligned.m8n8.x4.shared.b16 {%0,%1,%2,%3}, [%4];"
                 : "=r"(r[0]), "=r"(r[1]), "=r"(r[2]), "=r"(r[3]) : "r"(addr));
}
__device__ __forceinline__ void mma16816(float* d, const uint32_t* a,
                                         uint32_t b0, uint32_t b1) {
    asm volatile("mma.sync.aligned.m16n8k16.row.col.f32.bf16.bf16.f32 "
                 "{%0,%1,%2,%3}, {%4,%5,%6,%7}, {%8,%9}, {%0,%1,%2,%3};"
                 : "+f"(d[0]), "+f"(d[1]), "+f"(d[2]), "+f"(d[3])
                 : "r"(a[0]), "r"(a[1]), "r"(a[2]), "r"(a[3]), "r"(b0), "r"(b1));
}

// swizzled smem byte offset for [row][16B-chunk] of a 128x16 bf16 tile (32B rows)
__device__ __forceinline__ uint32_t swz(int row, int chunk) {
    return (uint32_t)(row * 32 + ((chunk ^ ((row >> 2) & 1)) << 4));
}

// ---------------- hi/lo bf16 split of fp32 inputs ----------------
__global__ void split_k(const float* __restrict__ src, int mode, int n4)
{
    int i = blockIdx.x * blockDim.x + threadIdx.x;
    if (i >= n4) return;
    __nv_bfloat16 *hi, *lo;
    size_t off = 0;
    if (mode == 0)      { hi = g_xh;  lo = g_xl; }
    else if (mode == 1) { hi = g_w1h; lo = g_w1l; }
    else if (mode == 2) { hi = g_w1h; lo = g_w1l; off = (size_t)2048 * 1024; }
    else                { hi = g_w2h; lo = g_w2l; }
    float4 v = ((const float4*)src)[i];
    float x[4] = {v.x, v.y, v.z, v.w};
    __align__(8) __nv_bfloat16 h[4];
    __align__(8) __nv_bfloat16 l[4];
    #pragma unroll
    for (int j = 0; j < 4; j++) {
        h[j] = __float2bfloat16(x[j]);
        l[j] = __float2bfloat16(x[j] - __bfloat162float(h[j]));
    }
    *(uint2*)(hi + off + (size_t)i * 4) = *(uint2*)h;
    *(uint2*)(lo + off + (size_t)i * 4) = *(uint2*)l;
}

// ---------------- HMMA bf16x3 GEMM: C[M,N] = A[M,K] * W[N,K]^T ------------
// 3-stage cp.async pipeline, 1 barrier/chunk, 2 CTAs/SM.
// mode 0: A = x(hi/lo), B = [gate_w|value_w](hi/lo), C = g_G, sigmoid+bias cols<nsplit
// mode 1: A = h(hi/lo), B = out_w(hi/lo),            C = Cext (y)
__global__ __launch_bounds__(256, 2)
void tc_gemm(int mode, const float* __restrict__ bias, float* __restrict__ Cext,
             int N, int nsplit)
{
    // [stage][array: Ah,Al,Bh,Bl][128*16 bf16] = 3 x 16KB = 48KB
    __shared__ __align__(1024) __nv_bfloat16 sm[NSTAGE][4][128 * BK];

    const int tid = threadIdx.x;
    const int lane = tid & 31, warp = tid >> 5;
    const int wm = warp & 3, wn = warp >> 2;       // warp grid 4 (m) x 2 (n)
    const int m0 = blockIdx.y * 128, n0 = blockIdx.x * 128;
    const int K = DM;                              // both GEMMs have K=1024

    const __nv_bfloat16 *Ah, *Al, *Bh, *Bl;
    float* C;
    if (mode == 0) { Ah = g_xh; Al = g_xl; Bh = g_w1h; Bl = g_w1l; C = g_G; }
    else           { Ah = g_hh; Al = g_hl; Bh = g_w2h; Bl = g_w2l; C = Cext; }

    // global load coords: 256 threads x 16B covers one 128x16 bf16 array
    const int lrow = tid >> 1;            // 0..127
    const int lu   = tid & 1;             // 16B chunk within 32B row
    const uint32_t so = swz(lrow, lu);
    const size_t gA = (size_t)(m0 + lrow) * K + lu * 8;
    const size_t gB = (size_t)(n0 + lrow) * K + lu * 8;

    uint32_t sb[NSTAGE][4];
    #pragma unroll
    for (int s = 0; s < NSTAGE; s++)
        #pragma unroll
        for (int a = 0; a < 4; a++)
            sb[s][a] = smem_u32(&sm[s][a][0]);

    float acc[2][8][4] = {};

    // ldmatrix row/chunk within tile — fixed per thread
    const int fr = lane & 15;             // row within 16-row tile
    const int fh = lane >> 4;             // k half (16B chunk 0/1)

    // prologue: stages 0,1 = chunks 0,1
    #pragma unroll
    for (int s = 0; s < NSTAGE - 1; s++) {
        const size_t ko = (size_t)s * BK;
        cp16(sb[s][0] + so, Ah + gA + ko);
        cp16(sb[s][1] + so, Al + gA + ko);
        cp16(sb[s][2] + so, Bh + gB + ko);
        cp16(sb[s][3] + so, Bl + gB + ko);
        cp_commit();
    }

    const int NCH = K / BK;               // 64
    for (int ch = 0; ch < NCH; ch++) {
        const int st = ch % NSTAGE;
        asm volatile("cp.async.wait_group 1;");
        __syncthreads();                  // chunk ch visible; stage (ch+2)%3 free

        const int pc = ch + NSTAGE - 1;
        if (pc < NCH) {
            const int ps = pc % NSTAGE;
            const size_t ko = (size_t)pc * BK;
            cp16(sb[ps][0] + so, Ah + gA + ko);
            cp16(sb[ps][1] + so, Al + gA + ko);
            cp16(sb[ps][2] + so, Bh + gB + ko);
            cp16(sb[ps][3] + so, Bl + gB + ko);
        }
        cp_commit();                      // always commit (group accounting)

        // A fragments (reused across all nt)
        uint32_t ah[2][4], al[2][4];
        #pragma unroll
        for (int am = 0; am < 2; am++) {
            uint32_t off = swz(wm * 32 + am * 16 + fr, fh);
            ldsm4(ah[am], sb[st][0] + off);
            ldsm4(al[am], sb[st][1] + off);
        }
        // B fragments per nt (lower reg pressure; LDSM hides under MMA)
        #pragma unroll
        for (int nt = 0; nt < 4; nt++) {
            uint32_t bh[4], bl[4];
            uint32_t off = swz(wn * 64 + nt * 16 + fr, fh);
            ldsm4(bh, sb[st][2] + off);
            ldsm4(bl, sb[st][3] + off);
            #pragma unroll
            for (int am = 0; am < 2; am++) {
                mma16816(acc[am][nt * 2 + 0], ah[am], bh[0], bh[2]);
                mma16816(acc[am][nt * 2 + 1], ah[am], bh[1], bh[3]);
                mma16816(acc[am][nt * 2 + 0], ah[am], bl[0], bl[2]);
                mma16816(acc[am][nt * 2 + 1], ah[am], bl[1], bl[3]);
                mma16816(acc[am][nt * 2 + 0], al[am], bh[0], bh[2]);
                mma16816(acc[am][nt * 2 + 1], al[am], bh[1], bh[3]);
            }
        }
    }

    // epilogue: d0,d1 -> (row, col..col+1); d2,d3 -> (row+8, same cols)
    #pragma unroll
    for (int am = 0; am < 2; am++) {
        int row = m0 + wm * 32 + am * 16 + (lane >> 2);
        #pragma unroll
        for (int bn = 0; bn < 8; bn++) {
            int col = n0 + wn * 64 + bn * 8 + (lane & 3) * 2;
            float* d = acc[am][bn];
            float v0 = d[0], v1 = d[1], v2 = d[2], v3 = d[3];
            if (col < nsplit) {
                float b0 = bias[col], b1 = bias[col + 1];
                v0 = 1.f / (1.f + __expf(-(v0 + b0)));
                v1 = 1.f / (1.f + __expf(-(v1 + b1)));
                v2 = 1.f / (1.f + __expf(-(v2 + b0)));
                v3 = 1.f / (1.f + __expf(-(v3 + b1)));
            }
            *(float2*)(C + (size_t)row * N + col)       = make_float2(v0, v1);
            *(float2*)(C + (size_t)(row + 8) * N + col) = make_float2(v2, v3);
        }
    }
}

// ---------------- chunked scan ----------------
__global__ __launch_bounds__(HS) void scan_phase1()
{
    const int b = blockIdx.y, chunk = blockIdx.x, i = threadIdx.x;
    const int t0 = chunk * LCHUNK;
    const float* base = g_G + (size_t)(b * T_SZ + t0) * GN;
    float p = 1.f, hl = 0.f;
    for (int t = 0; t < LCHUNK; t++) {
        const float* row = base + (size_t)t * GN;
        float a = row[i], ig = row[HS + i], v = row[2 * HS + i];
        p *= a;
        hl = fmaf(a, hl, ig * v);
    }
    const int c = b * HS + i;
    g_P [c * NCHUNK + chunk] = p;
    g_Hl[c * NCHUNK + chunk] = hl;
}

__global__ void scan_phase2(const float* __restrict__ h_prev,
                            float* __restrict__ h_last_out)
{
    const int c = blockIdx.x * blockDim.x + threadIdx.x;
    float carry = h_prev[c];
    #pragma unroll
    for (int j = 0; j < NCHUNK; j++) {
        g_C[c * NCHUNK + j] = carry;
        carry = fmaf(g_P[c * NCHUNK + j], carry, g_Hl[c * NCHUNK + j]);
    }
    h_last_out[c] = carry;
}

// phase3 emits h directly as bf16 hi/lo for GEMM2
__global__ __launch_bounds__(HS) void scan_phase3()
{
    const int b = blockIdx.y, chunk = blockIdx.x, i = threadIdx.x;
    const int c = b * HS + i;
    const int t0 = chunk * LCHUNK;
    const float* base = g_G + (size_t)(b * T_SZ + t0) * GN;
    const size_t hb = (size_t)(b * T_SZ + t0) * HS;

    float h = g_C[c * NCHUNK + chunk];
    for (int t = 0; t < LCHUNK; t++) {
        const float* row = base + (size_t)t * GN;
        float a = row[i], ig = row[HS + i], v = row[2 * HS + i];
        h = fmaf(a, h, ig * v);
        __nv_bfloat16 hh = __float2bfloat16(h);
        g_hh[hb + (size_t)t * HS + i] = hh;
        g_hl[hb + (size_t)t * HS + i] = __float2bfloat16(h - __bfloat162float(hh));
    }
}

// ---------------- launch ----------------
extern "C" void kernel_launch(void* const* d_in, const int* in_sizes, int n_in,
                              void* d_out, int out_size)
{
    const float* x       = (const float*)d_in[0];
    const float* h_prev  = (const float*)d_in[1];
    const float* gate_w  = (const float*)d_in[2];
    const float* gate_b  = (const float*)d_in[3];
    const float* value_w = (const float*)d_in[4];
    const float* out_w   = (const float*)d_in[5];

    float* y      = (float*)d_out;
    float* h_last = y + (size_t)M_SZ * DM;

    // hi/lo splits
    split_k<<<(M_SZ * DM / 4 + 255) / 256, 256>>>(x,       0, M_SZ * DM / 4);
    split_k<<<(2048 * 1024 / 4 + 255) / 256, 256>>>(gate_w, 1, 2048 * 1024 / 4);
    split_k<<<(1024 * 1024 / 4 + 255) / 256, 256>>>(value_w,2, 1024 * 1024 / 4);
    split_k<<<(1024 * 1024 / 4 + 255) / 256, 256>>>(out_w,  3, 1024 * 1024 / 4);

    // GEMM1: sigmoid(gates)+bias (cols<2048) and V -> g_G
    tc_gemm<<<dim3(GN / 128, M_SZ / 128), 256>>>(0, gate_b, nullptr, GN, 2048);

    // scan
    scan_phase1<<<dim3(NCHUNK, B_SZ), HS>>>();
    scan_phase2<<<B_SZ, HS>>>(h_prev, h_last);
    scan_phase3<<<dim3(NCHUNK, B_SZ), HS>>>();

    // GEMM2: y = h @ out_w^T
    tc_gemm<<<dim3(DM / 128, M_SZ / 128), 256>>>(1, nullptr, y, DM, 0);
}

// round 11
// speedup vs baseline: 2.3226x; 1.1104x over previous
#include <cuda_runtime.h>
#include <cuda_bf16.h>
#include <stdint.h>
#include <math.h>

#define B_SZ 4
#define T_SZ 4096
#define DM   1024
#define HS   1024
#define GN   3072
#define M_SZ (B_SZ * T_SZ)
#define NCHUNK 64
#define LCHUNK (T_SZ / NCHUNK)
#define BK 32                    // K per SMEM stage (two m16n8k16 k-steps)
#define NSTAGE 3
#define SM_BYTES (NSTAGE * 4 * 128 * BK * 2)   // 96 KB

// ---------------- scratch (device globals; allocation-free) ----------------
__device__ __align__(128) float g_G[(size_t)M_SZ * GN];     // sigmoid(gates) | V
__device__ __align__(128) float g_P [B_SZ * HS * NCHUNK];
__device__ __align__(128) float g_Hl[B_SZ * HS * NCHUNK];
__device__ __align__(128) float g_C [B_SZ * HS * NCHUNK];
__device__ __align__(128) __nv_bfloat16 g_xh[(size_t)M_SZ * DM], g_xl[(size_t)M_SZ * DM];
__device__ __align__(128) __nv_bfloat16 g_w1h[(size_t)GN * DM],  g_w1l[(size_t)GN * DM];
__device__ __align__(128) __nv_bfloat16 g_w2h[(size_t)DM * HS],  g_w2l[(size_t)DM * HS];
__device__ __align__(128) __nv_bfloat16 g_hh[(size_t)M_SZ * HS], g_hl[(size_t)M_SZ * HS];

// ---------------- PTX helpers ----------------
__device__ __forceinline__ uint32_t smem_u32(const void* p) {
    uint32_t a;
    asm("{ .reg .u64 t; cvta.to.shared.u64 t, %1; cvt.u32.u64 %0, t; }" : "=r"(a) : "l"(p));
    return a;
}
__device__ __forceinline__ void cp16(uint32_t s, const void* g) {
    asm volatile("cp.async.cg.shared.global [%0], [%1], 16;" :: "r"(s), "l"(g));
}
__device__ __forceinline__ void cp_commit() {
    asm volatile("cp.async.commit_group;");
}
__device__ __forceinline__ void ldsm4(uint32_t* r, uint32_t addr) {
    asm volatile("ldmatrix.sync.aligned.m8n8.x4.shared.b16 {%0,%1,%2,%3}, [%4];"
                 : "=r"(r[0]), "=r"(r[1]), "=r"(r[2]), "=r"(r[3]) : "r"(addr));
}
__device__ __forceinline__ void mma16816(float* d, const uint32_t* a,
                                         uint32_t b0, uint32_t b1) {
    asm volatile("mma.sync.aligned.m16n8k16.row.col.f32.bf16.bf16.f32 "
                 "{%0,%1,%2,%3}, {%4,%5,%6,%7}, {%8,%9}, {%0,%1,%2,%3};"
                 : "+f"(d[0]), "+f"(d[1]), "+f"(d[2]), "+f"(d[3])
                 : "r"(a[0]), "r"(a[1]), "r"(a[2]), "r"(a[3]), "r"(b0), "r"(b1));
}

// 64B-row swizzle: byte offset of [row][16B chunk c] within a 128x32 bf16 tile.
// chunk' = (c + (row>>1)) & 3 -> conflict-free for 8-lane ldmatrix phases
// (banks (4r + c') mod 8 all distinct) and for store phases.
__device__ __forceinline__ uint32_t swz32(int row, int c) {
    return (uint32_t)(row * 64 + (((c + (row >> 1)) & 3) << 4));
}

// ---------------- fused hi/lo bf16 split (single launch) ----------------
#define S_X  4194304u            // x:       16384*1024/4 float4
#define S_W1 524288u             // gate_w:   2048*1024/4
#define S_W2 262144u             // value_w:  1024*1024/4
#define S_W3 262144u             // out_w:    1024*1024/4
#define S_TOT (S_X + S_W1 + S_W2 + S_W3)

__global__ __launch_bounds__(256) void split_all(
    const float* __restrict__ x,  const float* __restrict__ gw,
    const float* __restrict__ vw, const float* __restrict__ ow)
{
    uint32_t i = blockIdx.x * blockDim.x + threadIdx.x;
    if (i >= S_TOT) return;
    const float* src;
    __nv_bfloat16 *hi, *lo;
    uint32_t li;
    if (i < S_X)                    { src = x;  hi = g_xh;  lo = g_xl;  li = i; }
    else if (i < S_X + S_W1)        { src = gw; hi = g_w1h; lo = g_w1l; li = i - S_X; }
    else if (i < S_X + S_W1 + S_W2) { src = vw; hi = g_w1h + (size_t)2048 * 1024;
                                      lo = g_w1l + (size_t)2048 * 1024; li = i - S_X - S_W1; }
    else                            { src = ow; hi = g_w2h; lo = g_w2l; li = i - S_X - S_W1 - S_W2; }
    float4 v = ((const float4*)src)[li];
    float xx[4] = {v.x, v.y, v.z, v.w};
    __align__(8) __nv_bfloat16 h[4];
    __align__(8) __nv_bfloat16 l[4];
    #pragma unroll
    for (int j = 0; j < 4; j++) {
        h[j] = __float2bfloat16(xx[j]);
        l[j] = __float2bfloat16(xx[j] - __bfloat162float(h[j]));
    }
    *(uint2*)(hi + (size_t)li * 4) = *(uint2*)h;
    *(uint2*)(lo + (size_t)li * 4) = *(uint2*)l;
}

// ---------------- HMMA bf16x3 GEMM: C[M,N] = A[M,K] * W[N,K]^T ------------
// BK=32, 3-stage dynamic-smem cp.async pipeline, 1 barrier per 32-K chunk, 2 CTAs/SM.
__global__ __launch_bounds__(256, 2)
void tc_gemm(int mode, const float* __restrict__ bias, float* __restrict__ Cext,
             int N, int nsplit)
{
    extern __shared__ __nv_bfloat16 smp[];   // [NSTAGE][4][128*BK]

    const int tid = threadIdx.x;
    const int lane = tid & 31, warp = tid >> 5;
    const int wm = warp & 3, wn = warp >> 2;       // warp grid 4 (m) x 2 (n)
    const int m0 = blockIdx.y * 128, n0 = blockIdx.x * 128;
    const int K = DM;

    const __nv_bfloat16 *Ah, *Al, *Bh, *Bl;
    float* C;
    if (mode == 0) { Ah = g_xh; Al = g_xl; Bh = g_w1h; Bl = g_w1l; C = g_G; }
    else           { Ah = g_hh; Al = g_hl; Bh = g_w2h; Bl = g_w2l; C = Cext; }

    uint32_t sb[NSTAGE][4];
    #pragma unroll
    for (int s = 0; s < NSTAGE; s++)
        #pragma unroll
        for (int a = 0; a < 4; a++)
            sb[s][a] = smem_u32(smp + ((size_t)(s * 4 + a)) * 128 * BK);

    // global->smem: 2 rounds of 256 threads x 16B per 8KB array
    uint32_t so[2];
    size_t goA[2], goB[2];
    #pragma unroll
    for (int i = 0; i < 2; i++) {
        int v = i * 256 + tid;
        int row = v >> 2, c = v & 3;
        so[i]  = swz32(row, c);
        goA[i] = (size_t)(m0 + row) * K + c * 8;
        goB[i] = (size_t)(n0 + row) * K + c * 8;
    }

    float acc[2][8][4] = {};
    const int fr = lane & 15;             // row within 16-row tile
    const int fh = lane >> 4;             // 16B half within a k16 step

    // prologue: stages 0,1 = chunks 0,1
    #pragma unroll
    for (int s = 0; s < NSTAGE - 1; s++) {
        const size_t ko = (size_t)s * BK;
        #pragma unroll
        for (int i = 0; i < 2; i++) {
            cp16(sb[s][0] + so[i], Ah + goA[i] + ko);
            cp16(sb[s][1] + so[i], Al + goA[i] + ko);
            cp16(sb[s][2] + so[i], Bh + goB[i] + ko);
            cp16(sb[s][3] + so[i], Bl + goB[i] + ko);
        }
        cp_commit();
    }

    const int NCH = K / BK;               // 32
    for (int ch = 0; ch < NCH; ch++) {
        const int st = ch % NSTAGE;
        asm volatile("cp.async.wait_group 1;");
        __syncthreads();                  // chunk ch visible; stage (ch+2)%3 free

        const int pc = ch + NSTAGE - 1;
        if (pc < NCH) {
            const int ps = pc % NSTAGE;
            const size_t ko = (size_t)pc * BK;
            #pragma unroll
            for (int i = 0; i < 2; i++) {
                cp16(sb[ps][0] + so[i], Ah + goA[i] + ko);
                cp16(sb[ps][1] + so[i], Al + goA[i] + ko);
                cp16(sb[ps][2] + so[i], Bh + goB[i] + ko);
                cp16(sb[ps][3] + so[i], Bl + goB[i] + ko);
            }
        }
        cp_commit();

        #pragma unroll
        for (int ks = 0; ks < 2; ks++) {  // two k16 steps within BK=32
            uint32_t ah[2][4], al[2][4];
            #pragma unroll
            for (int am = 0; am < 2; am++) {
                int row = wm * 32 + am * 16 + fr;
                uint32_t off = swz32(row, 2 * ks + fh);
                ldsm4(ah[am], sb[st][0] + off);
                ldsm4(al[am], sb[st][1] + off);
            }
            #pragma unroll
            for (int nt = 0; nt < 4; nt++) {
                uint32_t bh[4], bl[4];
                int row = wn * 64 + nt * 16 + fr;
                uint32_t off = swz32(row, 2 * ks + fh);
                ldsm4(bh, sb[st][2] + off);
                ldsm4(bl, sb[st][3] + off);
                #pragma unroll
                for (int am = 0; am < 2; am++) {
                    mma16816(acc[am][nt * 2 + 0], ah[am], bh[0], bh[2]);
                    mma16816(acc[am][nt * 2 + 1], ah[am], bh[1], bh[3]);
                    mma16816(acc[am][nt * 2 + 0], ah[am], bl[0], bl[2]);
                    mma16816(acc[am][nt * 2 + 1], ah[am], bl[1], bl[3]);
                    mma16816(acc[am][nt * 2 + 0], al[am], bh[0], bh[2]);
                    mma16816(acc[am][nt * 2 + 1], al[am], bh[1], bh[3]);
                }
            }
        }
    }

    // epilogue
    #pragma unroll
    for (int am = 0; am < 2; am++) {
        int row = m0 + wm * 32 + am * 16 + (lane >> 2);
        #pragma unroll
        for (int bn = 0; bn < 8; bn++) {
            int col = n0 + wn * 64 + bn * 8 + (lane & 3) * 2;
            float* d = acc[am][bn];
            float v0 = d[0], v1 = d[1], v2 = d[2], v3 = d[3];
            if (col < nsplit) {
                float b0 = bias[col], b1 = bias[col + 1];
                v0 = 1.f / (1.f + __expf(-(v0 + b0)));
                v1 = 1.f / (1.f + __expf(-(v1 + b1)));
                v2 = 1.f / (1.f + __expf(-(v2 + b0)));
                v3 = 1.f / (1.f + __expf(-(v3 + b1)));
            }
            *(float2*)(C + (size_t)row * N + col)       = make_float2(v0, v1);
            *(float2*)(C + (size_t)(row + 8) * N + col) = make_float2(v2, v3);
        }
    }
}

// ---------------- chunked scan ----------------
__global__ __launch_bounds__(HS) void scan_phase1()
{
    const int b = blockIdx.y, chunk = blockIdx.x, i = threadIdx.x;
    const int t0 = chunk * LCHUNK;
    const float* base = g_G + (size_t)(b * T_SZ + t0) * GN;
    float p = 1.f, hl = 0.f;
    for (int t = 0; t < LCHUNK; t++) {
        const float* row = base + (size_t)t * GN;
        float a = __ldcs(row + i), ig = __ldcs(row + HS + i), v = __ldcs(row + 2 * HS + i);
        p *= a;
        hl = fmaf(a, hl, ig * v);
    }
    const int c = b * HS + i;
    g_P [c * NCHUNK + chunk] = p;
    g_Hl[c * NCHUNK + chunk] = hl;
}

__global__ void scan_phase2(const float* __restrict__ h_prev,
                            float* __restrict__ h_last_out)
{
    const int c = blockIdx.x * blockDim.x + threadIdx.x;
    float carry = h_prev[c];
    #pragma unroll
    for (int j = 0; j < NCHUNK; j++) {
        g_C[c * NCHUNK + j] = carry;
        carry = fmaf(g_P[c * NCHUNK + j], carry, g_Hl[c * NCHUNK + j]);
    }
    h_last_out[c] = carry;
}

__global__ __launch_bounds__(HS) void scan_phase3()
{
    const int b = blockIdx.y, chunk = blockIdx.x, i = threadIdx.x;
    const int c = b * HS + i;
    const int t0 = chunk * LCHUNK;
    const float* base = g_G + (size_t)(b * T_SZ + t0) * GN;
    const size_t hb = (size_t)(b * T_SZ + t0) * HS;

    float h = g_C[c * NCHUNK + chunk];
    for (int t = 0; t < LCHUNK; t++) {
        const float* row = base + (size_t)t * GN;
        float a = __ldcs(row + i), ig = __ldcs(row + HS + i), v = __ldcs(row + 2 * HS + i);
        h = fmaf(a, h, ig * v);
        __nv_bfloat16 hh = __float2bfloat16(h);
        g_hh[hb + (size_t)t * HS + i] = hh;
        g_hl[hb + (size_t)t * HS + i] = __float2bfloat16(h - __bfloat162float(hh));
    }
}

// ---------------- launch ----------------
extern "C" void kernel_launch(void* const* d_in, const int* in_sizes, int n_in,
                              void* d_out, int out_size)
{
    const float* x       = (const float*)d_in[0];
    const float* h_prev  = (const float*)d_in[1];
    const float* gate_w  = (const float*)d_in[2];
    const float* gate_b  = (const float*)d_in[3];
    const float* value_w = (const float*)d_in[4];
    const float* out_w   = (const float*)d_in[5];

    float* y      = (float*)d_out;
    float* h_last = y + (size_t)M_SZ * DM;

    // one-time opt-in for 96KB dynamic smem (host-side config; deterministic)
    static cudaError_t attr_rc =
        cudaFuncSetAttribute(tc_gemm, cudaFuncAttributeMaxDynamicSharedMemorySize, SM_BYTES);
    (void)attr_rc;

    // fused hi/lo splits (one launch)
    split_all<<<(S_TOT + 255) / 256, 256>>>(x, gate_w, value_w, out_w);

    // GEMM1: sigmoid(gates)+bias (cols<2048) and V -> g_G
    tc_gemm<<<dim3(GN / 128, M_SZ / 128), 256, SM_BYTES>>>(0, gate_b, nullptr, GN, 2048);

    // scan
    scan_phase1<<<dim3(NCHUNK, B_SZ), HS>>>();
    scan_phase2<<<B_SZ, HS>>>(h_prev, h_last);
    scan_phase3<<<dim3(NCHUNK, B_SZ), HS>>>();

    // GEMM2: y = h @ out_w^T
    tc_gemm<<<dim3(DM / 128, M_SZ / 128), 256, SM_BYTES>>>(1, nullptr, y, DM, 0);
}

// round 14
// speedup vs baseline: 2.3333x; 1.0046x over previous
#include <cuda_runtime.h>
#include <cuda_bf16.h>
#include <stdint.h>
#include <math.h>

#define B_SZ 4
#define T_SZ 4096
#define DM   1024
#define HS   1024
#define GN   3072
#define M_SZ (B_SZ * T_SZ)
#define NCHUNK 64
#define LCHUNK (T_SZ / NCHUNK)
#define BK 32                    // K per SMEM stage (two m16n8k16 k-steps)
#define NSTAGE 3
#define SM_BYTES (NSTAGE * 4 * 128 * BK * 2)   // 96 KB

// ---------------- scratch (device globals; allocation-free) ----------------
__device__ __align__(128) float g_a [(size_t)M_SZ * HS];   // forget gate (fp32)
__device__ __align__(128) float g_ig[(size_t)M_SZ * HS];   // input gate (fp32)
__device__ __align__(128) float g_v [(size_t)M_SZ * HS];   // value (fp32)
__device__ __align__(128) float g_P [B_SZ * HS * NCHUNK];
__device__ __align__(128) float g_Hl[B_SZ * HS * NCHUNK];
__device__ __align__(128) float g_C [B_SZ * HS * NCHUNK];
__device__ __align__(128) __nv_bfloat16 g_xh[(size_t)M_SZ * DM], g_xl[(size_t)M_SZ * DM];
__device__ __align__(128) __nv_bfloat16 g_w1h[(size_t)GN * DM],  g_w1l[(size_t)GN * DM];
__device__ __align__(128) __nv_bfloat16 g_w2h[(size_t)DM * HS],  g_w2l[(size_t)DM * HS];
__device__ __align__(128) __nv_bfloat16 g_hh[(size_t)M_SZ * HS], g_hl[(size_t)M_SZ * HS];

// ---------------- PTX helpers ----------------
__device__ __forceinline__ uint32_t smem_u32(const void* p) {
    uint32_t a;
    asm("{ .reg .u64 t; cvta.to.shared.u64 t, %1; cvt.u32.u64 %0, t; }" : "=r"(a) : "l"(p));
    return a;
}
__device__ __forceinline__ void cp16(uint32_t s, const void* g) {
    asm volatile("cp.async.cg.shared.global [%0], [%1], 16;" :: "r"(s), "l"(g));
}
__device__ __forceinline__ void cp_commit() {
    asm volatile("cp.async.commit_group;");
}
__device__ __forceinline__ void ldsm4(uint32_t* r, uint32_t addr) {
    asm volatile("ldmatrix.sync.aligned.m8n8.x4.shared.b16 {%0,%1,%2,%3}, [%4];"
                 : "=r"(r[0]), "=r"(r[1]), "=r"(r[2]), "=r"(r[3]) : "r"(addr));
}
__device__ __forceinline__ void mma16816(float* d, const uint32_t* a,
                                         uint32_t b0, uint32_t b1) {
    asm volatile("mma.sync.aligned.m16n8k16.row.col.f32.bf16.bf16.f32 "
                 "{%0,%1,%2,%3}, {%4,%5,%6,%7}, {%8,%9}, {%0,%1,%2,%3};"
                 : "+f"(d[0]), "+f"(d[1]), "+f"(d[2]), "+f"(d[3])
                 : "r"(a[0]), "r"(a[1]), "r"(a[2]), "r"(a[3]), "r"(b0), "r"(b1));
}

// 64B-row swizzle (conflict-free for ldmatrix 8-lane phases and store phases)
__device__ __forceinline__ uint32_t swz32(int row, int c) {
    return (uint32_t)(row * 64 + (((c + (row >> 1)) & 3) << 4));
}

// ---------------- fused hi/lo bf16 split (single launch) ----------------
#define S_X  4194304u
#define S_W1 524288u
#define S_W2 262144u
#define S_W3 262144u
#define S_TOT (S_X + S_W1 + S_W2 + S_W3)

__global__ __launch_bounds__(256) void split_all(
    const float* __restrict__ x,  const float* __restrict__ gw,
    const float* __restrict__ vw, const float* __restrict__ ow)
{
    uint32_t i = blockIdx.x * blockDim.x + threadIdx.x;
    if (i >= S_TOT) return;
    const float* src;
    __nv_bfloat16 *hi, *lo;
    uint32_t li;
    if (i < S_X)                    { src = x;  hi = g_xh;  lo = g_xl;  li = i; }
    else if (i < S_X + S_W1)        { src = gw; hi = g_w1h; lo = g_w1l; li = i - S_X; }
    else if (i < S_X + S_W1 + S_W2) { src = vw; hi = g_w1h + (size_t)2048 * 1024;
                                      lo = g_w1l + (size_t)2048 * 1024; li = i - S_X - S_W1; }
    else                            { src = ow; hi = g_w2h; lo = g_w2l; li = i - S_X - S_W1 - S_W2; }
    float4 v = ((const float4*)src)[li];
    float xx[4] = {v.x, v.y, v.z, v.w};
    __align__(8) __nv_bfloat16 h[4];
    __align__(8) __nv_bfloat16 l[4];
    #pragma unroll
    for (int j = 0; j < 4; j++) {
        h[j] = __float2bfloat16(xx[j]);
        l[j] = __float2bfloat16(xx[j] - __bfloat162float(h[j]));
    }
    *(uint2*)(hi + (size_t)li * 4) = *(uint2*)h;
    *(uint2*)(lo + (size_t)li * 4) = *(uint2*)l;
}

// ---------------- HMMA bf16x3 GEMM: C[M,N] = A[M,K] * W[N,K]^T ------------
// BK=32, 3-stage dynamic-smem cp.async pipeline, 1 barrier per chunk, 2 CTAs/SM.
// mode 0: epilogue -> g_a | g_ig (sigmoid+bias) | g_v, all fp32
// mode 1: y = h @ out_w^T -> Cext fp32
__global__ __launch_bounds__(256, 2)
void tc_gemm(int mode, const float* __restrict__ bias, float* __restrict__ Cext, int N)
{
    extern __shared__ __nv_bfloat16 smp[];   // [NSTAGE][4][128*BK]

    const int tid = threadIdx.x;
    const int lane = tid & 31, warp = tid >> 5;
    const int wm = warp & 3, wn = warp >> 2;       // warp grid 4 (m) x 2 (n)
    const int m0 = blockIdx.y * 128, n0 = blockIdx.x * 128;
    const int K = DM;

    const __nv_bfloat16 *Ah, *Al, *Bh, *Bl;
    if (mode == 0) { Ah = g_xh; Al = g_xl; Bh = g_w1h; Bl = g_w1l; }
    else           { Ah = g_hh; Al = g_hl; Bh = g_w2h; Bl = g_w2l; }

    uint32_t sb[NSTAGE][4];
    #pragma unroll
    for (int s = 0; s < NSTAGE; s++)
        #pragma unroll
        for (int a = 0; a < 4; a++)
            sb[s][a] = smem_u32(smp + ((size_t)(s * 4 + a)) * 128 * BK);

    uint32_t so[2];
    size_t goA[2], goB[2];
    #pragma unroll
    for (int i = 0; i < 2; i++) {
        int v = i * 256 + tid;
        int row = v >> 2, c = v & 3;
        so[i]  = swz32(row, c);
        goA[i] = (size_t)(m0 + row) * K + c * 8;
        goB[i] = (size_t)(n0 + row) * K + c * 8;
    }

    float acc[2][8][4] = {};
    const int fr = lane & 15;
    const int fh = lane >> 4;

    #pragma unroll
    for (int s = 0; s < NSTAGE - 1; s++) {
        const size_t ko = (size_t)s * BK;
        #pragma unroll
        for (int i = 0; i < 2; i++) {
            cp16(sb[s][0] + so[i], Ah + goA[i] + ko);
            cp16(sb[s][1] + so[i], Al + goA[i] + ko);
            cp16(sb[s][2] + so[i], Bh + goB[i] + ko);
            cp16(sb[s][3] + so[i], Bl + goB[i] + ko);
        }
        cp_commit();
    }

    const int NCH = K / BK;               // 32
    for (int ch = 0; ch < NCH; ch++) {
        const int st = ch % NSTAGE;
        asm volatile("cp.async.wait_group 1;");
        __syncthreads();

        const int pc = ch + NSTAGE - 1;
        if (pc < NCH) {
            const int ps = pc % NSTAGE;
            const size_t ko = (size_t)pc * BK;
            #pragma unroll
            for (int i = 0; i < 2; i++) {
                cp16(sb[ps][0] + so[i], Ah + goA[i] + ko);
                cp16(sb[ps][1] + so[i], Al + goA[i] + ko);
                cp16(sb[ps][2] + so[i], Bh + goB[i] + ko);
                cp16(sb[ps][3] + so[i], Bl + goB[i] + ko);
            }
        }
        cp_commit();

        #pragma unroll
        for (int ks = 0; ks < 2; ks++) {
            uint32_t ah[2][4], al[2][4];
            #pragma unroll
            for (int am = 0; am < 2; am++) {
                int row = wm * 32 + am * 16 + fr;
                uint32_t off = swz32(row, 2 * ks + fh);
                ldsm4(ah[am], sb[st][0] + off);
                ldsm4(al[am], sb[st][1] + off);
            }
            #pragma unroll
            for (int nt = 0; nt < 4; nt++) {
                uint32_t bh[4], bl[4];
                int row = wn * 64 + nt * 16 + fr;
                uint32_t off = swz32(row, 2 * ks + fh);
                ldsm4(bh, sb[st][2] + off);
                ldsm4(bl, sb[st][3] + off);
                #pragma unroll
                for (int am = 0; am < 2; am++) {
                    mma16816(acc[am][nt * 2 + 0], ah[am], bh[0], bh[2]);
                    mma16816(acc[am][nt * 2 + 1], ah[am], bh[1], bh[3]);
                    mma16816(acc[am][nt * 2 + 0], ah[am], bl[0], bl[2]);
                    mma16816(acc[am][nt * 2 + 1], ah[am], bl[1], bl[3]);
                    mma16816(acc[am][nt * 2 + 0], al[am], bh[0], bh[2]);
                    mma16816(acc[am][nt * 2 + 1], al[am], bh[1], bh[3]);
                }
            }
        }
    }

    // epilogue
    const int seg = n0 >> 10;                     // mode 0: 0=a, 1=ig, 2=v
    #pragma unroll
    for (int am = 0; am < 2; am++) {
        int row = m0 + wm * 32 + am * 16 + (lane >> 2);
        #pragma unroll
        for (int bn = 0; bn < 8; bn++) {
            int col = n0 + wn * 64 + bn * 8 + (lane & 3) * 2;
            float* d = acc[am][bn];
            float v0 = d[0], v1 = d[1], v2 = d[2], v3 = d[3];
            if (mode == 1) {
                *(float2*)(Cext + (size_t)row * N + col)       = make_float2(v0, v1);
                *(float2*)(Cext + (size_t)(row + 8) * N + col) = make_float2(v2, v3);
            } else {
                const int lcol = col & 1023;
                if (seg < 2) {   // sigmoid(gate + bias)
                    float b0 = bias[col], b1 = bias[col + 1];
                    v0 = 1.f / (1.f + __expf(-(v0 + b0)));
                    v1 = 1.f / (1.f + __expf(-(v1 + b1)));
                    v2 = 1.f / (1.f + __expf(-(v2 + b0)));
                    v3 = 1.f / (1.f + __expf(-(v3 + b1)));
                }
                float* dst = (seg == 0) ? g_a : (seg == 1) ? g_ig : g_v;
                *(float2*)(dst + (size_t)row * HS + lcol)       = make_float2(v0, v1);
                *(float2*)(dst + (size_t)(row + 8) * HS + lcol) = make_float2(v2, v3);
            }
        }
    }
}

// ---------------- chunked scan (256 threads x 4 channels, float4) ----------
__global__ __launch_bounds__(256) void scan_phase1()
{
    const int b = blockIdx.y, chunk = blockIdx.x;
    const int i4 = threadIdx.x * 4;               // first of 4 channels
    const int t0 = chunk * LCHUNK;
    const size_t rb = (size_t)(b * T_SZ + t0) * HS + i4;

    float p[4] = {1.f, 1.f, 1.f, 1.f}, hl[4] = {};
    for (int t = 0; t < LCHUNK; t++) {
        const size_t o = rb + (size_t)t * HS;
        float4 a  = __ldcs((const float4*)(g_a  + o));
        float4 ig = __ldcs((const float4*)(g_ig + o));
        float4 v  = __ldcs((const float4*)(g_v  + o));
        const float* ap = &a.x;
        const float* gp = &ig.x;
        const float* vp = &v.x;
        #pragma unroll
        for (int j = 0; j < 4; j++) {
            p[j] *= ap[j];
            hl[j] = fmaf(ap[j], hl[j], gp[j] * vp[j]);
        }
    }
    #pragma unroll
    for (int j = 0; j < 4; j++) {
        const int c = b * HS + i4 + j;
        g_P [c * NCHUNK + chunk] = p[j];
        g_Hl[c * NCHUNK + chunk] = hl[j];
    }
}

__global__ __launch_bounds__(128) void scan_phase2(const float* __restrict__ h_prev,
                                                   float* __restrict__ h_last_out)
{
    const int c = blockIdx.x * blockDim.x + threadIdx.x;   // 32 blocks x 128
    float carry = h_prev[c];
    #pragma unroll
    for (int j = 0; j < NCHUNK; j++) {
        g_C[c * NCHUNK + j] = carry;
        carry = fmaf(g_P[c * NCHUNK + j], carry, g_Hl[c * NCHUNK + j]);
    }
    h_last_out[c] = carry;
}

__global__ __launch_bounds__(256) void scan_phase3()
{
    const int b = blockIdx.y, chunk = blockIdx.x;
    const int i4 = threadIdx.x * 4;
    const int t0 = chunk * LCHUNK;
    const size_t rb = (size_t)(b * T_SZ + t0) * HS + i4;

    float h[4];
    #pragma unroll
    for (int j = 0; j < 4; j++)
        h[j] = g_C[(b * HS + i4 + j) * NCHUNK + chunk];

    for (int t = 0; t < LCHUNK; t++) {
        const size_t o = rb + (size_t)t * HS;
        float4 a  = __ldcs((const float4*)(g_a  + o));
        float4 ig = __ldcs((const float4*)(g_ig + o));
        float4 v  = __ldcs((const float4*)(g_v  + o));
        const float* ap = &a.x;
        const float* gp = &ig.x;
        const float* vp = &v.x;
        __align__(8) __nv_bfloat16 hh[4];
        __align__(8) __nv_bfloat16 hlq[4];
        #pragma unroll
        for (int j = 0; j < 4; j++) {
            h[j] = fmaf(ap[j], h[j], gp[j] * vp[j]);
            hh[j]  = __float2bfloat16(h[j]);
            hlq[j] = __float2bfloat16(h[j] - __bfloat162float(hh[j]));
        }
        *(uint2*)(g_hh + o) = *(uint2*)hh;
        *(uint2*)(g_hl + o) = *(uint2*)hlq;
    }
}

// ---------------- launch ----------------
extern "C" void kernel_launch(void* const* d_in, const int* in_sizes, int n_in,
                              void* d_out, int out_size)
{
    const float* x       = (const float*)d_in[0];
    const float* h_prev  = (const float*)d_in[1];
    const float* gate_w  = (const float*)d_in[2];
    const float* gate_b  = (const float*)d_in[3];
    const float* value_w = (const float*)d_in[4];
    const float* out_w   = (const float*)d_in[5];

    float* y      = (float*)d_out;
    float* h_last = y + (size_t)M_SZ * DM;

    static cudaError_t attr_rc =
        cudaFuncSetAttribute(tc_gemm, cudaFuncAttributeMaxDynamicSharedMemorySize, SM_BYTES);
    (void)attr_rc;

    split_all<<<(S_TOT + 255) / 256, 256>>>(x, gate_w, value_w, out_w);

    // GEMM1: sigmoid(gates)+bias / V -> g_a | g_ig | g_v (fp32)
    tc_gemm<<<dim3(GN / 128, M_SZ / 128), 256, SM_BYTES>>>(0, gate_b, nullptr, GN);

    // scan
    scan_phase1<<<dim3(NCHUNK, B_SZ), 256>>>();
    scan_phase2<<<32, 128>>>(h_prev, h_last);
    scan_phase3<<<dim3(NCHUNK, B_SZ), 256>>>();

    // GEMM2: y = h @ out_w^T
    tc_gemm<<<dim3(DM / 128, M_SZ / 128), 256, SM_BYTES>>>(1, nullptr, y, DM);
}

// round 15
// speedup vs baseline: 3.9422x; 1.6895x over previous
#include <cuda_runtime.h>
#include <cuda_bf16.h>
#include <stdint.h>
#include <math.h>

#define B_SZ 4
#define T_SZ 4096
#define DM   1024
#define HS   1024
#define GN   3072
#define M_SZ (B_SZ * T_SZ)
#define NCHUNK 64
#define LCHUNK (T_SZ / NCHUNK)
#define BK 32                    // fp32 K per SMEM stage (four m16n8k8 steps)
#define NSTAGE 3
#define SM_BYTES (NSTAGE * 2 * 128 * BK * 4)   // 96 KB

// ---------------- scratch (device globals; allocation-free) ----------------
__device__ __align__(128) float g_a [(size_t)M_SZ * HS];   // forget gate (fp32)
__device__ __align__(128) float g_ig[(size_t)M_SZ * HS];   // input gate (fp32)
__device__ __align__(128) float g_v [(size_t)M_SZ * HS];   // value (fp32)
__device__ __align__(128) float g_P [B_SZ * HS * NCHUNK];
__device__ __align__(128) float g_Hl[B_SZ * HS * NCHUNK];
__device__ __align__(128) float g_C [B_SZ * HS * NCHUNK];
__device__ __align__(128) float g_xr [(size_t)M_SZ * DM];  // tf32-rounded x
__device__ __align__(128) float g_w1r[(size_t)GN * DM];    // tf32-rounded [gate_w|value_w]
__device__ __align__(128) float g_w2r[(size_t)DM * HS];    // tf32-rounded out_w
__device__ __align__(128) float g_hr [(size_t)M_SZ * HS];  // tf32-rounded h

// ---------------- PTX helpers ----------------
__device__ __forceinline__ uint32_t smem_u32(const void* p) {
    uint32_t a;
    asm("{ .reg .u64 t; cvta.to.shared.u64 t, %1; cvt.u32.u64 %0, t; }" : "=r"(a) : "l"(p));
    return a;
}
__device__ __forceinline__ void cp16(uint32_t s, const void* g) {
    asm volatile("cp.async.cg.shared.global [%0], [%1], 16;" :: "r"(s), "l"(g));
}
__device__ __forceinline__ void cp_commit() {
    asm volatile("cp.async.commit_group;");
}
__device__ __forceinline__ void ldsm4(uint32_t* r, uint32_t addr) {
    asm volatile("ldmatrix.sync.aligned.m8n8.x4.shared.b16 {%0,%1,%2,%3}, [%4];"
                 : "=r"(r[0]), "=r"(r[1]), "=r"(r[2]), "=r"(r[3]) : "r"(addr));
}
__device__ __forceinline__ void mma_tf32(float* d, const uint32_t* a,
                                         uint32_t b0, uint32_t b1) {
    asm volatile("mma.sync.aligned.m16n8k8.row.col.f32.tf32.tf32.f32 "
                 "{%0,%1,%2,%3}, {%4,%5,%6,%7}, {%8,%9}, {%0,%1,%2,%3};"
                 : "+f"(d[0]), "+f"(d[1]), "+f"(d[2]), "+f"(d[3])
                 : "r"(a[0]), "r"(a[1]), "r"(a[2]), "r"(a[3]), "r"(b0), "r"(b1));
}
__device__ __forceinline__ float tf32r(float x) {
    float o;
    asm("cvt.rna.tf32.f32 %0, %1;" : "=f"(o) : "f"(x));
    return o;
}

// fp32-tile swizzle: 128B rows (32 fp32), 8 chunks of 16B; chunk' = chunk ^ (row&7)
__device__ __forceinline__ uint32_t swzf(int row, int c) {
    return (uint32_t)(row * 128 + (((c ^ row) & 7) << 4));
}

// ---------------- tf32 pre-round of x and weights (single launch) ----------
#define R_X  4194304u
#define R_W1 524288u
#define R_W2 262144u
#define R_W3 262144u
#define R_TOT (R_X + R_W1 + R_W2 + R_W3)

__global__ __launch_bounds__(256) void round_all(
    const float* __restrict__ x,  const float* __restrict__ gw,
    const float* __restrict__ vw, const float* __restrict__ ow)
{
    uint32_t i = blockIdx.x * blockDim.x + threadIdx.x;
    if (i >= R_TOT) return;
    const float* src;
    float* dst;
    uint32_t li;
    if (i < R_X)                    { src = x;  dst = g_xr;  li = i; }
    else if (i < R_X + R_W1)        { src = gw; dst = g_w1r; li = i - R_X; }
    else if (i < R_X + R_W1 + R_W2) { src = vw; dst = g_w1r + (size_t)2048 * 1024; li = i - R_X - R_W1; }
    else                            { src = ow; dst = g_w2r; li = i - R_X - R_W1 - R_W2; }
    float4 v = ((const float4*)src)[li];
    v.x = tf32r(v.x); v.y = tf32r(v.y); v.z = tf32r(v.z); v.w = tf32r(v.w);
    ((float4*)dst)[li] = v;
}

// ---------------- tf32 HMMA GEMM: C[M,N] = A[M,K] * W[N,K]^T ---------------
// BK=32 fp32, 3-stage cp.async pipeline, 1 barrier/chunk, 2 CTAs/SM.
// mode 0: A=g_xr, B=g_w1r; epilogue -> g_a | g_ig (sigmoid+bias) | g_v (fp32)
// mode 1: A=g_hr, B=g_w2r; -> Cext fp32
__global__ __launch_bounds__(256, 2)
void tc_gemm(int mode, const float* __restrict__ bias, float* __restrict__ Cext, int N)
{
    extern __shared__ float smp[];   // [NSTAGE][2][128*BK]

    const int tid = threadIdx.x;
    const int lane = tid & 31, warp = tid >> 5;
    const int wm = warp & 3, wn = warp >> 2;       // warp grid 4 (m) x 2 (n)
    const int m0 = blockIdx.y * 128, n0 = blockIdx.x * 128;
    const int K = DM;

    const float *A, *B;
    if (mode == 0) { A = g_xr; B = g_w1r; }
    else           { A = g_hr; B = g_w2r; }

    uint32_t sbA[NSTAGE], sbB[NSTAGE];
    #pragma unroll
    for (int s = 0; s < NSTAGE; s++) {
        sbA[s] = smem_u32(smp + (size_t)(s * 2 + 0) * 128 * BK);
        sbB[s] = smem_u32(smp + (size_t)(s * 2 + 1) * 128 * BK);
    }

    // global->smem: 4 rounds of 256 threads x 16B per 16KB array
    uint32_t so[4];
    size_t goA[4], goB[4];
    #pragma unroll
    for (int i = 0; i < 4; i++) {
        int v = i * 256 + tid;
        int row = v >> 3, c = v & 7;
        so[i]  = swzf(row, c);
        goA[i] = (size_t)(m0 + row) * K + c * 4;
        goB[i] = (size_t)(n0 + row) * K + c * 4;
    }

    float acc[2][8][4] = {};

    // ldmatrix lane-address components (fixed per thread)
    const int a_row = wm * 32 + ((lane >> 3) & 1) * 8 + (lane & 7);  // + am*16
    const int a_cx  = (lane >> 4) & 1;                               // chunk +0/+1
    const int b_rowb = wn * 64 + ((lane >> 4) & 1) * 8 + (lane & 7); // + p*16
    const int b_cx  = (lane >> 3) & 1;

    // prologue: stages 0,1 = chunks 0,1
    #pragma unroll
    for (int s = 0; s < NSTAGE - 1; s++) {
        const size_t ko = (size_t)s * BK;
        #pragma unroll
        for (int i = 0; i < 4; i++) {
            cp16(sbA[s] + so[i], A + goA[i] + ko);
            cp16(sbB[s] + so[i], B + goB[i] + ko);
        }
        cp_commit();
    }

    const int NCH = K / BK;               // 32
    for (int ch = 0; ch < NCH; ch++) {
        const int st = ch % NSTAGE;
        asm volatile("cp.async.wait_group 1;");
        __syncthreads();                  // chunk ch visible; stage (ch+2)%3 free

        const int pc = ch + NSTAGE - 1;
        if (pc < NCH) {
            const int ps = pc % NSTAGE;
            const size_t ko = (size_t)pc * BK;
            #pragma unroll
            for (int i = 0; i < 4; i++) {
                cp16(sbA[ps] + so[i], A + goA[i] + ko);
                cp16(sbB[ps] + so[i], B + goB[i] + ko);
            }
        }
        cp_commit();

        #pragma unroll
        for (int j = 0; j < 4; j++) {     // four k8 steps within BK=32
            // A fragments: x4 = exact m16n8k8 tf32 layout (a0..a3)
            uint32_t a0[4], a1[4];
            ldsm4(a0, sbA[st] + swzf(a_row,      2 * j + a_cx));
            ldsm4(a1, sbA[st] + swzf(a_row + 16, 2 * j + a_cx));
            #pragma unroll
            for (int p = 0; p < 4; p++) { // B n8-tile pairs (2p, 2p+1)
                uint32_t bb[4];           // [b0,b1] of tile 2p, [b0,b1] of tile 2p+1
                ldsm4(bb, sbB[st] + swzf(b_rowb + p * 16, 2 * j + b_cx));
                mma_tf32(acc[0][2 * p + 0], a0, bb[0], bb[1]);
                mma_tf32(acc[0][2 * p + 1], a0, bb[2], bb[3]);
                mma_tf32(acc[1][2 * p + 0], a1, bb[0], bb[1]);
                mma_tf32(acc[1][2 * p + 1], a1, bb[2], bb[3]);
            }
        }
    }

    // epilogue (same C fragment layout as m16n8k16)
    const int seg = n0 >> 10;                     // mode 0: 0=a, 1=ig, 2=v
    #pragma unroll
    for (int am = 0; am < 2; am++) {
        int row = m0 + wm * 32 + am * 16 + (lane >> 2);
        #pragma unroll
        for (int bn = 0; bn < 8; bn++) {
            int col = n0 + wn * 64 + bn * 8 + (lane & 3) * 2;
            float* d = acc[am][bn];
            float v0 = d[0], v1 = d[1], v2 = d[2], v3 = d[3];
            if (mode == 1) {
                *(float2*)(Cext + (size_t)row * N + col)       = make_float2(v0, v1);
                *(float2*)(Cext + (size_t)(row + 8) * N + col) = make_float2(v2, v3);
            } else {
                const int lcol = col & 1023;
                if (seg < 2) {   // sigmoid(gate + bias)
                    float b0 = bias[col], b1 = bias[col + 1];
                    v0 = 1.f / (1.f + __expf(-(v0 + b0)));
                    v1 = 1.f / (1.f + __expf(-(v1 + b1)));
                    v2 = 1.f / (1.f + __expf(-(v2 + b0)));
                    v3 = 1.f / (1.f + __expf(-(v3 + b1)));
                }
                float* dst = (seg == 0) ? g_a : (seg == 1) ? g_ig : g_v;
                *(float2*)(dst + (size_t)row * HS + lcol)       = make_float2(v0, v1);
                *(float2*)(dst + (size_t)(row + 8) * HS + lcol) = make_float2(v2, v3);
            }
        }
    }
}

// ---------------- chunked scan (256 threads x 4 channels, float4) ----------
__global__ __launch_bounds__(256) void scan_phase1()
{
    const int b = blockIdx.y, chunk = blockIdx.x;
    const int i4 = threadIdx.x * 4;
    const int t0 = chunk * LCHUNK;
    const size_t rb = (size_t)(b * T_SZ + t0) * HS + i4;

    float p[4] = {1.f, 1.f, 1.f, 1.f}, hl[4] = {};
    for (int t = 0; t < LCHUNK; t++) {
        const size_t o = rb + (size_t)t * HS;
        float4 a  = __ldcs((const float4*)(g_a  + o));
        float4 ig = __ldcs((const float4*)(g_ig + o));
        float4 v  = __ldcs((const float4*)(g_v  + o));
        const float* ap = &a.x;
        const float* gp = &ig.x;
        const float* vp = &v.x;
        #pragma unroll
        for (int j = 0; j < 4; j++) {
            p[j] *= ap[j];
            hl[j] = fmaf(ap[j], hl[j], gp[j] * vp[j]);
        }
    }
    #pragma unroll
    for (int j = 0; j < 4; j++) {
        const int c = b * HS + i4 + j;
        g_P [c * NCHUNK + chunk] = p[j];
        g_Hl[c * NCHUNK + chunk] = hl[j];
    }
}

__global__ __launch_bounds__(128) void scan_phase2(const float* __restrict__ h_prev,
                                                   float* __restrict__ h_last_out)
{
    const int c = blockIdx.x * blockDim.x + threadIdx.x;   // 32 blocks x 128
    float carry = h_prev[c];
    #pragma unroll
    for (int j = 0; j < NCHUNK; j++) {
        g_C[c * NCHUNK + j] = carry;
        carry = fmaf(g_P[c * NCHUNK + j], carry, g_Hl[c * NCHUNK + j]);
    }
    h_last_out[c] = carry;
}

// phase3 emits h pre-rounded to tf32 (RNE) for GEMM2
__global__ __launch_bounds__(256) void scan_phase3()
{
    const int b = blockIdx.y, chunk = blockIdx.x;
    const int i4 = threadIdx.x * 4;
    const int t0 = chunk * LCHUNK;
    const size_t rb = (size_t)(b * T_SZ + t0) * HS + i4;

    float h[4];
    #pragma unroll
    for (int j = 0; j < 4; j++)
        h[j] = g_C[(b * HS + i4 + j) * NCHUNK + chunk];

    for (int t = 0; t < LCHUNK; t++) {
        const size_t o = rb + (size_t)t * HS;
        float4 a  = __ldcs((const float4*)(g_a  + o));
        float4 ig = __ldcs((const float4*)(g_ig + o));
        float4 v  = __ldcs((const float4*)(g_v  + o));
        const float* ap = &a.x;
        const float* gp = &ig.x;
        const float* vp = &v.x;
        float4 hq;
        float* hqp = &hq.x;
        #pragma unroll
        for (int j = 0; j < 4; j++) {
            h[j] = fmaf(ap[j], h[j], gp[j] * vp[j]);
            hqp[j] = tf32r(h[j]);
        }
        *(float4*)(g_hr + o) = hq;
    }
}

// ---------------- launch ----------------
extern "C" void kernel_launch(void* const* d_in, const int* in_sizes, int n_in,
                              void* d_out, int out_size)
{
    const float* x       = (const float*)d_in[0];
    const float* h_prev  = (const float*)d_in[1];
    const float* gate_w  = (const float*)d_in[2];
    const float* gate_b  = (const float*)d_in[3];
    const float* value_w = (const float*)d_in[4];
    const float* out_w   = (const float*)d_in[5];

    float* y      = (float*)d_out;
    float* h_last = y + (size_t)M_SZ * DM;

    static cudaError_t attr_rc =
        cudaFuncSetAttribute(tc_gemm, cudaFuncAttributeMaxDynamicSharedMemorySize, SM_BYTES);
    (void)attr_rc;

    // tf32 pre-round (RNE) of x and all weights
    round_all<<<(R_TOT + 255) / 256, 256>>>(x, gate_w, value_w, out_w);

    // GEMM1: sigmoid(gates)+bias / V -> g_a | g_ig | g_v (fp32)
    tc_gemm<<<dim3(GN / 128, M_SZ / 128), 256, SM_BYTES>>>(0, gate_b, nullptr, GN);

    // scan
    scan_phase1<<<dim3(NCHUNK, B_SZ), 256>>>();
    scan_phase2<<<32, 128>>>(h_prev, h_last);
    scan_phase3<<<dim3(NCHUNK, B_SZ), 256>>>();

    // GEMM2: y = h @ out_w^T
    tc_gemm<<<dim3(DM / 128, M_SZ / 128), 256, SM_BYTES>>>(1, nullptr, y, DM);
}